// round 2
// baseline (speedup 1.0000x reference)
#include <cuda_runtime.h>

#define B      128
#define IN     256
#define HS     512
#define OUT    256
#define CHUNK  32     // batches per L2-reuse chunk
#define KB     16     // batches per K1 block

__device__ float g_da[B];

// ---------------------------------------------------------------------------
// K1: hactiv[b,i] = tanh( pre(b,i) + sum_j (w[i,j]+alpha[i,j]*hebb[b,i,j])*hidden[b,j] )
// One warp per row i; weights in registers; 16 batches' hidden+inputs preloaded
// to smem ONCE; no barriers in the main loop; batch loop unrolled x2 for MLP.
// ---------------------------------------------------------------------------
__global__ __launch_bounds__(256) void k1_hactiv(
    const float* __restrict__ inputs, const float* __restrict__ hidden,
    const float* __restrict__ hebb,   const float* __restrict__ i2h_w,
    const float* __restrict__ i2h_b,  const float* __restrict__ w,
    const float* __restrict__ alpha,  float* __restrict__ hactiv, int b0)
{
    const int tid   = threadIdx.x;
    const int warp  = tid >> 5;
    const int lane  = tid & 31;
    const int i     = blockIdx.x * 8 + warp;
    const int bbase = b0 + blockIdx.y * KB;

    __shared__ float4 shH[KB * HS / 4];   // 2048 f4 = 32 KB
    __shared__ float4 shX[KB * IN / 4];   // 1024 f4 = 16 KB

    // one-time preload of the whole batch sub-chunk (rows contiguous in gmem)
    const float4* gh = (const float4*)(hidden + (size_t)bbase * HS);
    for (int t = tid; t < KB * HS / 4; t += 256) shH[t] = gh[t];
    const float4* gx = (const float4*)(inputs + (size_t)bbase * IN);
    for (int t = tid; t < KB * IN / 4; t += 256) shX[t] = gx[t];

    // per-lane register copies of this row's static weights
    float4 wr[4], ar[4], iw[2];
    const float4* w4 = (const float4*)(w     + (size_t)i * HS);
    const float4* a4 = (const float4*)(alpha + (size_t)i * HS);
    const float4* x4 = (const float4*)(i2h_w + (size_t)i * IN);
#pragma unroll
    for (int k = 0; k < 4; ++k) { wr[k] = w4[lane + 32 * k]; ar[k] = a4[lane + 32 * k]; }
#pragma unroll
    for (int k = 0; k < 2; ++k) { iw[k] = x4[lane + 32 * k]; }
    const float bias = i2h_b[i];

    __syncthreads();   // smem preload visible; the ONLY block barrier

#pragma unroll 2
    for (int bb = 0; bb < KB; bb += 2) {
        const float4* h0 = (const float4*)(hebb + ((size_t)(bbase + bb)     * HS + i) * HS);
        const float4* h1 = (const float4*)(hebb + ((size_t)(bbase + bb + 1) * HS + i) * HS);
        float4 a0[4], a1[4];
#pragma unroll
        for (int k = 0; k < 4; ++k) { a0[k] = h0[lane + 32 * k]; a1[k] = h1[lane + 32 * k]; }

        float s0 = 0.f, s1 = 0.f;
#pragma unroll
        for (int k = 0; k < 4; ++k) {
            const float4 d0 = shH[bb * (HS / 4) + lane + 32 * k];
            const float4 d1 = shH[(bb + 1) * (HS / 4) + lane + 32 * k];
            s0 = fmaf(fmaf(ar[k].x, a0[k].x, wr[k].x), d0.x, s0);
            s0 = fmaf(fmaf(ar[k].y, a0[k].y, wr[k].y), d0.y, s0);
            s0 = fmaf(fmaf(ar[k].z, a0[k].z, wr[k].z), d0.z, s0);
            s0 = fmaf(fmaf(ar[k].w, a0[k].w, wr[k].w), d0.w, s0);
            s1 = fmaf(fmaf(ar[k].x, a1[k].x, wr[k].x), d1.x, s1);
            s1 = fmaf(fmaf(ar[k].y, a1[k].y, wr[k].y), d1.y, s1);
            s1 = fmaf(fmaf(ar[k].z, a1[k].z, wr[k].z), d1.z, s1);
            s1 = fmaf(fmaf(ar[k].w, a1[k].w, wr[k].w), d1.w, s1);
        }
#pragma unroll
        for (int k = 0; k < 2; ++k) {
            const float4 x0 = shX[bb * (IN / 4) + lane + 32 * k];
            const float4 x1 = shX[(bb + 1) * (IN / 4) + lane + 32 * k];
            s0 = fmaf(iw[k].x, x0.x, s0); s0 = fmaf(iw[k].y, x0.y, s0);
            s0 = fmaf(iw[k].z, x0.z, s0); s0 = fmaf(iw[k].w, x0.w, s0);
            s1 = fmaf(iw[k].x, x1.x, s1); s1 = fmaf(iw[k].y, x1.y, s1);
            s1 = fmaf(iw[k].z, x1.z, s1); s1 = fmaf(iw[k].w, x1.w, s1);
        }
#pragma unroll
        for (int off = 16; off; off >>= 1) {
            s0 += __shfl_xor_sync(0xffffffffu, s0, off);
            s1 += __shfl_xor_sync(0xffffffffu, s1, off);
        }
        if (lane == 0) {
            hactiv[(size_t)(bbase + bb)     * HS + i] = tanhf(s0 + bias);
            hactiv[(size_t)(bbase + bb + 1) * HS + i] = tanhf(s1 + bias);
        }
    }
}

// ---------------------------------------------------------------------------
// K2: per-sample heads; one block per batch sample in the chunk.
// ---------------------------------------------------------------------------
__global__ __launch_bounds__(256) void k2_heads(
    const float* __restrict__ hactiv, const float* __restrict__ h2o_w,
    const float* __restrict__ h2o_b,  const float* __restrict__ h2v_w,
    const float* __restrict__ h2v_b,  const float* __restrict__ h2da_w,
    const float* __restrict__ h2da_b, float* __restrict__ activout,
    float* __restrict__ valueout, int b0)
{
    const int b = b0 + blockIdx.x;
    const int t = threadIdx.x;
    __shared__ float sh[HS];
    sh[t]       = hactiv[(size_t)b * HS + t];
    sh[t + 256] = hactiv[(size_t)b * HS + t + 256];
    __syncthreads();

    const float4* wrow = (const float4*)(h2o_w + (size_t)t * HS);
    float s = 0.f;
#pragma unroll 8
    for (int f = 0; f < HS / 4; ++f) {
        const float4 wv = wrow[f];
        s = fmaf(wv.x, sh[4 * f + 0], s);
        s = fmaf(wv.y, sh[4 * f + 1], s);
        s = fmaf(wv.z, sh[4 * f + 2], s);
        s = fmaf(wv.w, sh[4 * f + 3], s);
    }
    activout[(size_t)b * OUT + t] = s + h2o_b[t];

    float pv = fmaf(h2v_w [t], sh[t], h2v_w [t + 256] * sh[t + 256]);
    float pd = fmaf(h2da_w[t], sh[t], h2da_w[t + 256] * sh[t + 256]);
#pragma unroll
    for (int off = 16; off; off >>= 1) {
        pv += __shfl_xor_sync(0xffffffffu, pv, off);
        pd += __shfl_xor_sync(0xffffffffu, pd, off);
    }
    __shared__ float rv[8], rd[8];
    if ((t & 31) == 0) { rv[t >> 5] = pv; rd[t >> 5] = pd; }
    __syncthreads();
    if (t == 0) {
        float v = 0.f, d = 0.f;
#pragma unroll
        for (int k = 0; k < 8; ++k) { v += rv[k]; d += rd[k]; }
        valueout[b] = v + h2v_b[0];
        g_da[b]     = tanhf(d + h2da_b[0]);
    }
}

// ---------------------------------------------------------------------------
// K3: hebb_new = clip(hebb + da[b]*hactiv[b,i]*hidden[b,j], ±1).
// Runs right after K1/K2 of the same 32-batch chunk so hebb reads hit L2.
// ---------------------------------------------------------------------------
__global__ __launch_bounds__(256) void k3_hebb(
    const float* __restrict__ hebb,   const float* __restrict__ hidden,
    const float* __restrict__ hactiv, float* __restrict__ hebb_new, int b0)
{
    const size_t base = (size_t)b0 * HS * (HS / 4) + (size_t)blockIdx.x * 1024;
    const float4* hb = (const float4*)hebb;
    const float4* hd = (const float4*)hidden;
    float4*       ob = (float4*)hebb_new;
#pragma unroll
    for (int u = 0; u < 4; ++u) {
        const size_t idx = base + (size_t)u * 256 + threadIdx.x;
        const int row = (int)(idx >> 7);        // b*HS + i
        const int f   = (int)(idx & 127);
        const int b   = row >> 9;
        const float coef = g_da[b] * hactiv[row];
        const float4 x = hd[b * (HS / 4) + f];
        const float4 h = hb[idx];
        float4 r;
        r.x = fminf(1.f, fmaxf(-1.f, fmaf(coef, x.x, h.x)));
        r.y = fminf(1.f, fmaxf(-1.f, fmaf(coef, x.y, h.y)));
        r.z = fminf(1.f, fmaxf(-1.f, fmaf(coef, x.z, h.z)));
        r.w = fminf(1.f, fmaxf(-1.f, fmaf(coef, x.w, h.w)));
        ob[idx] = r;
    }
}

// ---------------------------------------------------------------------------
extern "C" void kernel_launch(void* const* d_in, const int* in_sizes, int n_in,
                              void* d_out, int out_size)
{
    const float* inputs = (const float*)d_in[0];
    const float* hidden = (const float*)d_in[1];
    const float* hebb   = (const float*)d_in[2];
    const float* i2h_w  = (const float*)d_in[3];
    const float* i2h_b  = (const float*)d_in[4];
    const float* w      = (const float*)d_in[5];
    const float* alpha  = (const float*)d_in[6];
    const float* h2o_w  = (const float*)d_in[7];
    const float* h2o_b  = (const float*)d_in[8];
    const float* h2v_w  = (const float*)d_in[9];
    const float* h2v_b  = (const float*)d_in[10];
    const float* h2da_w = (const float*)d_in[11];
    const float* h2da_b = (const float*)d_in[12];

    float* out      = (float*)d_out;
    float* activout = out;                                // [B, OUT]
    float* valueout = activout + (size_t)B * OUT;         // [B, 1]
    float* hactiv   = valueout + B;                       // [B, HS]
    float* hebb_new = hactiv + (size_t)B * HS;            // [B, HS, HS]

    for (int b0 = 0; b0 < B; b0 += CHUNK) {
        k1_hactiv<<<dim3(HS / 8, CHUNK / KB), 256>>>(
            inputs, hidden, hebb, i2h_w, i2h_b, w, alpha, hactiv, b0);
        k2_heads<<<CHUNK, 256>>>(
            hactiv, h2o_w, h2o_b, h2v_w, h2v_b, h2da_w, h2da_b,
            activout, valueout, b0);
        k3_hebb<<<CHUNK * HS * (HS / 4) / 1024, 256>>>(
            hebb, hidden, hactiv, hebb_new, b0);
    }
}

// round 4
// speedup vs baseline: 1.2872x; 1.2872x over previous
#include <cuda_runtime.h>

#define B      128
#define IN     256
#define HS     512
#define OUT    256
#define CHUNK  32     // batches per L2-reuse chunk
#define KB     4      // batches per K1 block

__device__ float g_da[B];

// ---------------------------------------------------------------------------
// K1: hactiv[b,i] = tanh( pre(b,i) + sum_j (w[i,j]+alpha[i,j]*hebb[b,i,j])*hidden[b,j] )
// One warp per row i, KB=4 batches per block. Weights in registers, the 4
// hidden/input rows preloaded to smem once; no barriers in the main loop.
// ---------------------------------------------------------------------------
__global__ __launch_bounds__(256, 2) void k1_hactiv(
    const float* __restrict__ inputs, const float* __restrict__ hidden,
    const float* __restrict__ hebb,   const float* __restrict__ i2h_w,
    const float* __restrict__ i2h_b,  const float* __restrict__ w,
    const float* __restrict__ alpha,  float* __restrict__ hactiv, int b0)
{
    const int tid   = threadIdx.x;
    const int warp  = tid >> 5;
    const int lane  = tid & 31;
    const int i     = blockIdx.x * 8 + warp;
    const int bbase = b0 + blockIdx.y * KB;

    __shared__ float4 shH[KB * HS / 4];   // 512 f4 = 8 KB
    __shared__ float4 shX[KB * IN / 4];   // 256 f4 = 4 KB

    // one-time preload (KB rows are contiguous in gmem)
    const float4* gh = (const float4*)(hidden + (size_t)bbase * HS);
    for (int t = tid; t < KB * HS / 4; t += 256) shH[t] = gh[t];
    const float4* gx = (const float4*)(inputs + (size_t)bbase * IN);
    { const int t = tid; if (t < KB * IN / 4) shX[t] = gx[t]; }

    // per-lane register copies of this row's static weights
    float4 wr[4], ar[4], iw[2];
    const float4* w4 = (const float4*)(w     + (size_t)i * HS);
    const float4* a4 = (const float4*)(alpha + (size_t)i * HS);
    const float4* x4 = (const float4*)(i2h_w + (size_t)i * IN);
#pragma unroll
    for (int k = 0; k < 4; ++k) { wr[k] = w4[lane + 32 * k]; ar[k] = a4[lane + 32 * k]; }
#pragma unroll
    for (int k = 0; k < 2; ++k) { iw[k] = x4[lane + 32 * k]; }
    const float bias = i2h_b[i];

    __syncthreads();   // the ONLY block barrier

#pragma unroll
    for (int bb = 0; bb < KB; bb += 2) {
        const float4* h0 = (const float4*)(hebb + ((size_t)(bbase + bb)     * HS + i) * HS);
        const float4* h1 = (const float4*)(hebb + ((size_t)(bbase + bb + 1) * HS + i) * HS);
        float4 a0[4], a1[4];
#pragma unroll
        for (int k = 0; k < 4; ++k) { a0[k] = h0[lane + 32 * k]; a1[k] = h1[lane + 32 * k]; }

        float s0 = 0.f, s1 = 0.f;
#pragma unroll
        for (int k = 0; k < 4; ++k) {
            const float4 d0 = shH[bb * (HS / 4) + lane + 32 * k];
            const float4 d1 = shH[(bb + 1) * (HS / 4) + lane + 32 * k];
            s0 = fmaf(fmaf(ar[k].x, a0[k].x, wr[k].x), d0.x, s0);
            s0 = fmaf(fmaf(ar[k].y, a0[k].y, wr[k].y), d0.y, s0);
            s0 = fmaf(fmaf(ar[k].z, a0[k].z, wr[k].z), d0.z, s0);
            s0 = fmaf(fmaf(ar[k].w, a0[k].w, wr[k].w), d0.w, s0);
            s1 = fmaf(fmaf(ar[k].x, a1[k].x, wr[k].x), d1.x, s1);
            s1 = fmaf(fmaf(ar[k].y, a1[k].y, wr[k].y), d1.y, s1);
            s1 = fmaf(fmaf(ar[k].z, a1[k].z, wr[k].z), d1.z, s1);
            s1 = fmaf(fmaf(ar[k].w, a1[k].w, wr[k].w), d1.w, s1);
        }
#pragma unroll
        for (int k = 0; k < 2; ++k) {
            const float4 x0 = shX[bb * (IN / 4) + lane + 32 * k];
            const float4 x1 = shX[(bb + 1) * (IN / 4) + lane + 32 * k];
            s0 = fmaf(iw[k].x, x0.x, s0); s0 = fmaf(iw[k].y, x0.y, s0);
            s0 = fmaf(iw[k].z, x0.z, s0); s0 = fmaf(iw[k].w, x0.w, s0);
            s1 = fmaf(iw[k].x, x1.x, s1); s1 = fmaf(iw[k].y, x1.y, s1);
            s1 = fmaf(iw[k].z, x1.z, s1); s1 = fmaf(iw[k].w, x1.w, s1);
        }
#pragma unroll
        for (int off = 16; off; off >>= 1) {
            s0 += __shfl_xor_sync(0xffffffffu, s0, off);
            s1 += __shfl_xor_sync(0xffffffffu, s1, off);
        }
        if (lane == 0) {
            hactiv[(size_t)(bbase + bb)     * HS + i] = tanhf(s0 + bias);
            hactiv[(size_t)(bbase + bb + 1) * HS + i] = tanhf(s1 + bias);
        }
    }
}

// ---------------------------------------------------------------------------
// K2: per-sample heads; one block per batch sample in the chunk.
// ---------------------------------------------------------------------------
__global__ __launch_bounds__(256) void k2_heads(
    const float* __restrict__ hactiv, const float* __restrict__ h2o_w,
    const float* __restrict__ h2o_b,  const float* __restrict__ h2v_w,
    const float* __restrict__ h2v_b,  const float* __restrict__ h2da_w,
    const float* __restrict__ h2da_b, float* __restrict__ activout,
    float* __restrict__ valueout, int b0)
{
    const int b = b0 + blockIdx.x;
    const int t = threadIdx.x;
    __shared__ float sh[HS];
    sh[t]       = hactiv[(size_t)b * HS + t];
    sh[t + 256] = hactiv[(size_t)b * HS + t + 256];
    __syncthreads();

    const float4* wrow = (const float4*)(h2o_w + (size_t)t * HS);
    float s = 0.f;
#pragma unroll 8
    for (int f = 0; f < HS / 4; ++f) {
        const float4 wv = wrow[f];
        s = fmaf(wv.x, sh[4 * f + 0], s);
        s = fmaf(wv.y, sh[4 * f + 1], s);
        s = fmaf(wv.z, sh[4 * f + 2], s);
        s = fmaf(wv.w, sh[4 * f + 3], s);
    }
    activout[(size_t)b * OUT + t] = s + h2o_b[t];

    float pv = fmaf(h2v_w [t], sh[t], h2v_w [t + 256] * sh[t + 256]);
    float pd = fmaf(h2da_w[t], sh[t], h2da_w[t + 256] * sh[t + 256]);
#pragma unroll
    for (int off = 16; off; off >>= 1) {
        pv += __shfl_xor_sync(0xffffffffu, pv, off);
        pd += __shfl_xor_sync(0xffffffffu, pd, off);
    }
    __shared__ float rv[8], rd[8];
    if ((t & 31) == 0) { rv[t >> 5] = pv; rd[t >> 5] = pd; }
    __syncthreads();
    if (t == 0) {
        float v = 0.f, d = 0.f;
#pragma unroll
        for (int k = 0; k < 8; ++k) { v += rv[k]; d += rd[k]; }
        valueout[b] = v + h2v_b[0];
        g_da[b]     = tanhf(d + h2da_b[0]);
    }
}

// ---------------------------------------------------------------------------
// K3: hebb_new = clip(hebb + da[b]*hactiv[b,i]*hidden[b,j], ±1).
// Runs right after K1/K2 of the same chunk: hebb reads should hit L2.
// __ldcs on reads (dead after use) and __stcs on writes (never re-read)
// keep K3's own traffic from evicting the chunk.
// ---------------------------------------------------------------------------
__global__ __launch_bounds__(256) void k3_hebb(
    const float* __restrict__ hebb,   const float* __restrict__ hidden,
    const float* __restrict__ hactiv, float* __restrict__ hebb_new, int b0)
{
    const size_t base = (size_t)b0 * HS * (HS / 4) + (size_t)blockIdx.x * 1024;
    const float4* hb = (const float4*)hebb;
    const float4* hd = (const float4*)hidden;
    float4*       ob = (float4*)hebb_new;
#pragma unroll
    for (int u = 0; u < 4; ++u) {
        const size_t idx = base + (size_t)u * 256 + threadIdx.x;
        const int row = (int)(idx >> 7);        // b*HS + i
        const int f   = (int)(idx & 127);
        const int b   = row >> 9;
        const float coef = g_da[b] * hactiv[row];
        const float4 x = hd[b * (HS / 4) + f];
        const float4 h = __ldcs(hb + idx);
        float4 r;
        r.x = fminf(1.f, fmaxf(-1.f, fmaf(coef, x.x, h.x)));
        r.y = fminf(1.f, fmaxf(-1.f, fmaf(coef, x.y, h.y)));
        r.z = fminf(1.f, fmaxf(-1.f, fmaf(coef, x.z, h.z)));
        r.w = fminf(1.f, fmaxf(-1.f, fmaf(coef, x.w, h.w)));
        __stcs(ob + idx, r);
    }
}

// ---------------------------------------------------------------------------
extern "C" void kernel_launch(void* const* d_in, const int* in_sizes, int n_in,
                              void* d_out, int out_size)
{
    const float* inputs = (const float*)d_in[0];
    const float* hidden = (const float*)d_in[1];
    const float* hebb   = (const float*)d_in[2];
    const float* i2h_w  = (const float*)d_in[3];
    const float* i2h_b  = (const float*)d_in[4];
    const float* w      = (const float*)d_in[5];
    const float* alpha  = (const float*)d_in[6];
    const float* h2o_w  = (const float*)d_in[7];
    const float* h2o_b  = (const float*)d_in[8];
    const float* h2v_w  = (const float*)d_in[9];
    const float* h2v_b  = (const float*)d_in[10];
    const float* h2da_w = (const float*)d_in[11];
    const float* h2da_b = (const float*)d_in[12];

    float* out      = (float*)d_out;
    float* activout = out;                                // [B, OUT]
    float* valueout = activout + (size_t)B * OUT;         // [B, 1]
    float* hactiv   = valueout + B;                       // [B, HS]
    float* hebb_new = hactiv + (size_t)B * HS;            // [B, HS, HS]

    for (int b0 = 0; b0 < B; b0 += CHUNK) {
        k1_hactiv<<<dim3(HS / 8, CHUNK / KB), 256>>>(
            inputs, hidden, hebb, i2h_w, i2h_b, w, alpha, hactiv, b0);
        k2_heads<<<CHUNK, 256>>>(
            hactiv, h2o_w, h2o_b, h2v_w, h2v_b, h2da_w, h2da_b,
            activout, valueout, b0);
        k3_hebb<<<CHUNK * HS * (HS / 4) / 1024, 256>>>(
            hebb, hidden, hactiv, hebb_new, b0);
    }
}

// round 5
// speedup vs baseline: 2.1844x; 1.6969x over previous
#include <cuda_runtime.h>

#define B      128
#define IN     256
#define HS     512
#define OUT    256
#define RG     8      // rows per CTA (one warp per row)
#define SG     8      // samples per CTA
#define NCTA_PER_SAMPLE (HS / RG)   // 64

__device__ float        g_acc_da[B];
__device__ unsigned int g_cnt[B];

// ---------------------------------------------------------------------------
// K0: zero the cross-CTA accumulators (runs every replay, before K1).
// ---------------------------------------------------------------------------
__global__ void k0_init()
{
    const int t = threadIdx.x;
    if (t < B) { g_acc_da[t] = 0.f; g_cnt[t] = 0u; }
}

// ---------------------------------------------------------------------------
// K1 (fused): phase1 computes hactiv for this CTA's 8 rows x 8 samples
// (hebb read -> allocates in L2), contributes da partials via atomics;
// after a gpu-scope spin on the per-sample counter, phase3 re-reads the SAME
// hebb rows (L2 hits) and writes the clipped update with __stcs.
// ---------------------------------------------------------------------------
__global__ __launch_bounds__(256, 2) void k1_fused(
    const float* __restrict__ inputs, const float* __restrict__ hidden,
    const float* __restrict__ hebb,   const float* __restrict__ i2h_w,
    const float* __restrict__ i2h_b,  const float* __restrict__ w,
    const float* __restrict__ alpha,  const float* __restrict__ h2da_w,
    const float* __restrict__ h2da_b, float* __restrict__ hactiv,
    float* __restrict__ hebb_new)
{
    const int tid   = threadIdx.x;
    const int warp  = tid >> 5;
    const int lane  = tid & 31;
    const int i     = blockIdx.x * RG + warp;
    const int bbase = blockIdx.y * SG;

    __shared__ float4 shH[SG * HS / 4];    // 16 KB
    __shared__ float4 shX[SG * IN / 4];    //  8 KB
    __shared__ float  sh_hact[SG * RG];
    __shared__ float  sh_wda[RG];
    __shared__ float  sh_da[SG];

    // preload 8 samples' hidden + inputs (contiguous rows)
    const float4* gh = (const float4*)(hidden + (size_t)bbase * HS);
    for (int t = tid; t < SG * HS / 4; t += 256) shH[t] = gh[t];
    const float4* gx = (const float4*)(inputs + (size_t)bbase * IN);
    for (int t = tid; t < SG * IN / 4; t += 256) shX[t] = gx[t];
    if (tid < RG) sh_wda[tid] = h2da_w[blockIdx.x * RG + tid];

    // per-lane register copies of this row's static weights
    float4 wr[4], ar[4], iw[2];
    const float4* w4 = (const float4*)(w     + (size_t)i * HS);
    const float4* a4 = (const float4*)(alpha + (size_t)i * HS);
    const float4* x4 = (const float4*)(i2h_w + (size_t)i * IN);
#pragma unroll
    for (int k = 0; k < 4; ++k) { wr[k] = w4[lane + 32 * k]; ar[k] = a4[lane + 32 * k]; }
#pragma unroll
    for (int k = 0; k < 2; ++k) { iw[k] = x4[lane + 32 * k]; }
    const float bias = i2h_b[i];

    __syncthreads();

    // ---------------- phase 1: hactiv ----------------
#pragma unroll
    for (int bb = 0; bb < SG; bb += 2) {
        const float4* h0 = (const float4*)(hebb + ((size_t)(bbase + bb)     * HS + i) * HS);
        const float4* h1 = (const float4*)(hebb + ((size_t)(bbase + bb + 1) * HS + i) * HS);
        float4 a0[4], a1[4];
#pragma unroll
        for (int k = 0; k < 4; ++k) { a0[k] = h0[lane + 32 * k]; a1[k] = h1[lane + 32 * k]; }

        float s0 = 0.f, s1 = 0.f;
#pragma unroll
        for (int k = 0; k < 4; ++k) {
            const float4 d0 = shH[bb * (HS / 4) + lane + 32 * k];
            const float4 d1 = shH[(bb + 1) * (HS / 4) + lane + 32 * k];
            s0 = fmaf(fmaf(ar[k].x, a0[k].x, wr[k].x), d0.x, s0);
            s0 = fmaf(fmaf(ar[k].y, a0[k].y, wr[k].y), d0.y, s0);
            s0 = fmaf(fmaf(ar[k].z, a0[k].z, wr[k].z), d0.z, s0);
            s0 = fmaf(fmaf(ar[k].w, a0[k].w, wr[k].w), d0.w, s0);
            s1 = fmaf(fmaf(ar[k].x, a1[k].x, wr[k].x), d1.x, s1);
            s1 = fmaf(fmaf(ar[k].y, a1[k].y, wr[k].y), d1.y, s1);
            s1 = fmaf(fmaf(ar[k].z, a1[k].z, wr[k].z), d1.z, s1);
            s1 = fmaf(fmaf(ar[k].w, a1[k].w, wr[k].w), d1.w, s1);
        }
#pragma unroll
        for (int k = 0; k < 2; ++k) {
            const float4 x0 = shX[bb * (IN / 4) + lane + 32 * k];
            const float4 x1 = shX[(bb + 1) * (IN / 4) + lane + 32 * k];
            s0 = fmaf(iw[k].x, x0.x, s0); s0 = fmaf(iw[k].y, x0.y, s0);
            s0 = fmaf(iw[k].z, x0.z, s0); s0 = fmaf(iw[k].w, x0.w, s0);
            s1 = fmaf(iw[k].x, x1.x, s1); s1 = fmaf(iw[k].y, x1.y, s1);
            s1 = fmaf(iw[k].z, x1.z, s1); s1 = fmaf(iw[k].w, x1.w, s1);
        }
#pragma unroll
        for (int off = 16; off; off >>= 1) {
            s0 += __shfl_xor_sync(0xffffffffu, s0, off);
            s1 += __shfl_xor_sync(0xffffffffu, s1, off);
        }
        if (lane == 0) {
            const float h0v = tanhf(s0 + bias);
            const float h1v = tanhf(s1 + bias);
            hactiv[(size_t)(bbase + bb)     * HS + i] = h0v;
            hactiv[(size_t)(bbase + bb + 1) * HS + i] = h1v;
            sh_hact[bb * RG + warp]       = h0v;
            sh_hact[(bb + 1) * RG + warp] = h1v;
        }
    }
    __syncthreads();

    // ---------------- da partials + counter ----------------
    if (tid < SG) {
        const int b = bbase + tid;
        float sum = 0.f;
#pragma unroll
        for (int wv = 0; wv < RG; ++wv) sum += sh_wda[wv] * sh_hact[tid * RG + wv];
        atomicAdd(&g_acc_da[b], sum);
        __threadfence();
        atomicAdd(&g_cnt[b], 1u);
    }

    // ---------------- spin until all 64 CTAs of each sample arrived --------
    if (tid < SG) {
        const int b = bbase + tid;
        unsigned c;
        do {
            asm volatile("ld.acquire.gpu.u32 %0, [%1];" : "=r"(c) : "l"(g_cnt + b));
            if (c < NCTA_PER_SAMPLE) __nanosleep(64);
        } while (c < NCTA_PER_SAMPLE);
        sh_da[tid] = tanhf(__ldcg(&g_acc_da[b]) + h2da_b[0]);
    }
    __syncthreads();

    // ---------------- phase 3: hebb update (L2-hit reads, streaming writes)
#pragma unroll 2
    for (int bb = 0; bb < SG; ++bb) {
        const float coef = sh_da[bb] * sh_hact[bb * RG + warp];
        const size_t roff = ((size_t)(bbase + bb) * HS + i) * HS;
        const float4* hb = (const float4*)(hebb + roff);
        float4*       ob = (float4*)(hebb_new + roff);
#pragma unroll
        for (int k = 0; k < 4; ++k) {
            const float4 h = hb[lane + 32 * k];
            const float4 x = shH[bb * (HS / 4) + lane + 32 * k];
            float4 r;
            r.x = fminf(1.f, fmaxf(-1.f, fmaf(coef, x.x, h.x)));
            r.y = fminf(1.f, fmaxf(-1.f, fmaf(coef, x.y, h.y)));
            r.z = fminf(1.f, fmaxf(-1.f, fmaf(coef, x.z, h.z)));
            r.w = fminf(1.f, fmaxf(-1.f, fmaf(coef, x.w, h.w)));
            __stcs(ob + lane + 32 * k, r);
        }
    }
}

// ---------------------------------------------------------------------------
// K2: activout + valueout (da no longer needed here).
// ---------------------------------------------------------------------------
__global__ __launch_bounds__(256) void k2_heads(
    const float* __restrict__ hactiv, const float* __restrict__ h2o_w,
    const float* __restrict__ h2o_b,  const float* __restrict__ h2v_w,
    const float* __restrict__ h2v_b,  float* __restrict__ activout,
    float* __restrict__ valueout)
{
    const int b = blockIdx.x;
    const int t = threadIdx.x;
    __shared__ float sh[HS];
    sh[t]       = hactiv[(size_t)b * HS + t];
    sh[t + 256] = hactiv[(size_t)b * HS + t + 256];
    __syncthreads();

    const float4* wrow = (const float4*)(h2o_w + (size_t)t * HS);
    float s = 0.f;
#pragma unroll 8
    for (int f = 0; f < HS / 4; ++f) {
        const float4 wv = wrow[f];
        s = fmaf(wv.x, sh[4 * f + 0], s);
        s = fmaf(wv.y, sh[4 * f + 1], s);
        s = fmaf(wv.z, sh[4 * f + 2], s);
        s = fmaf(wv.w, sh[4 * f + 3], s);
    }
    activout[(size_t)b * OUT + t] = s + h2o_b[t];

    float pv = fmaf(h2v_w[t], sh[t], h2v_w[t + 256] * sh[t + 256]);
#pragma unroll
    for (int off = 16; off; off >>= 1) pv += __shfl_xor_sync(0xffffffffu, pv, off);
    __shared__ float rv[8];
    if ((t & 31) == 0) rv[t >> 5] = pv;
    __syncthreads();
    if (t == 0) {
        float v = 0.f;
#pragma unroll
        for (int k = 0; k < 8; ++k) v += rv[k];
        valueout[b] = v + h2v_b[0];
    }
}

// ---------------------------------------------------------------------------
extern "C" void kernel_launch(void* const* d_in, const int* in_sizes, int n_in,
                              void* d_out, int out_size)
{
    const float* inputs = (const float*)d_in[0];
    const float* hidden = (const float*)d_in[1];
    const float* hebb   = (const float*)d_in[2];
    const float* i2h_w  = (const float*)d_in[3];
    const float* i2h_b  = (const float*)d_in[4];
    const float* w      = (const float*)d_in[5];
    const float* alpha  = (const float*)d_in[6];
    const float* h2o_w  = (const float*)d_in[7];
    const float* h2o_b  = (const float*)d_in[8];
    const float* h2v_w  = (const float*)d_in[9];
    const float* h2v_b  = (const float*)d_in[10];
    const float* h2da_w = (const float*)d_in[11];
    const float* h2da_b = (const float*)d_in[12];

    float* out      = (float*)d_out;
    float* activout = out;                                // [B, OUT]
    float* valueout = activout + (size_t)B * OUT;         // [B, 1]
    float* hactiv   = valueout + B;                       // [B, HS]
    float* hebb_new = hactiv + (size_t)B * HS;            // [B, HS, HS]

    k0_init<<<1, 128>>>();
    k1_fused<<<dim3(HS / RG, B / SG), 256>>>(
        inputs, hidden, hebb, i2h_w, i2h_b, w, alpha,
        h2da_w, h2da_b, hactiv, hebb_new);
    k2_heads<<<B, 256>>>(
        hactiv, h2o_w, h2o_b, h2v_w, h2v_b, activout, valueout);
}

// round 7
// speedup vs baseline: 2.4584x; 1.1254x over previous
#include <cuda_runtime.h>

#define B      128
#define IN     256
#define HS     512
#define OUT    256
#define RG     8      // rows per CTA (one warp per row)
#define SG     8      // samples per CTA
#define NCTA_PER_SAMPLE (HS / RG)   // 64

__device__ float        g_acc_da[B];   // zero at module load; left zero by kernel
__device__ unsigned int g_cnt[B];
__device__ unsigned int g_done[B];

// ---------------------------------------------------------------------------
// K1 (fused, self-resetting):
//  phase 1: hactiv for 8 rows x 8 samples (hebb read -> L2), da partials
//  spin:    per-sample counter until all 64 CTAs arrived
//  phase 3: hebb update (L2-hit reads via __ldcs, streaming __stcs writes)
//  heads:   activout/valueout computed by designated CTAs of each group
//  reset:   64th consumer per sample zeroes acc/cnt/done for next replay
// ---------------------------------------------------------------------------
__global__ __launch_bounds__(256, 2) void k1_fused(
    const float* __restrict__ inputs, const float* __restrict__ hidden,
    const float* __restrict__ hebb,   const float* __restrict__ i2h_w,
    const float* __restrict__ i2h_b,  const float* __restrict__ w,
    const float* __restrict__ alpha,  const float* __restrict__ h2da_w,
    const float* __restrict__ h2da_b, const float* __restrict__ h2o_w,
    const float* __restrict__ h2o_b,  const float* __restrict__ h2v_w,
    const float* __restrict__ h2v_b,  float* __restrict__ hactiv,
    float* __restrict__ hebb_new,     float* __restrict__ activout,
    float* __restrict__ valueout)
{
    const int tid   = threadIdx.x;
    const int warp  = tid >> 5;
    const int lane  = tid & 31;
    const int i     = blockIdx.x * RG + warp;
    const int bbase = blockIdx.y * SG;

    __shared__ float4 shH[SG * HS / 4];    // 16 KB
    __shared__ float4 shX[SG * IN / 4];    //  8 KB
    __shared__ float  sh_hact[SG * RG];
    __shared__ float  sh_wda[RG];
    __shared__ float  sh_da[SG];

    // preload 8 samples' hidden + inputs (contiguous rows)
    const float4* gh = (const float4*)(hidden + (size_t)bbase * HS);
    for (int t = tid; t < SG * HS / 4; t += 256) shH[t] = gh[t];
    const float4* gx = (const float4*)(inputs + (size_t)bbase * IN);
    for (int t = tid; t < SG * IN / 4; t += 256) shX[t] = gx[t];
    if (tid < RG) sh_wda[tid] = h2da_w[blockIdx.x * RG + tid];

    // per-lane register copies of this row's static weights
    float4 wr[4], ar[4], iw[2];
    const float4* w4 = (const float4*)(w     + (size_t)i * HS);
    const float4* a4 = (const float4*)(alpha + (size_t)i * HS);
    const float4* x4 = (const float4*)(i2h_w + (size_t)i * IN);
#pragma unroll
    for (int k = 0; k < 4; ++k) { wr[k] = w4[lane + 32 * k]; ar[k] = a4[lane + 32 * k]; }
#pragma unroll
    for (int k = 0; k < 2; ++k) { iw[k] = x4[lane + 32 * k]; }
    const float bias = i2h_b[i];

    __syncthreads();

    // ---------------- phase 1: hactiv ----------------
#pragma unroll
    for (int bb = 0; bb < SG; bb += 2) {
        const float4* h0 = (const float4*)(hebb + ((size_t)(bbase + bb)     * HS + i) * HS);
        const float4* h1 = (const float4*)(hebb + ((size_t)(bbase + bb + 1) * HS + i) * HS);
        float4 a0[4], a1[4];
#pragma unroll
        for (int k = 0; k < 4; ++k) { a0[k] = h0[lane + 32 * k]; a1[k] = h1[lane + 32 * k]; }

        float s0 = 0.f, s1 = 0.f;
#pragma unroll
        for (int k = 0; k < 4; ++k) {
            const float4 d0 = shH[bb * (HS / 4) + lane + 32 * k];
            const float4 d1 = shH[(bb + 1) * (HS / 4) + lane + 32 * k];
            s0 = fmaf(fmaf(ar[k].x, a0[k].x, wr[k].x), d0.x, s0);
            s0 = fmaf(fmaf(ar[k].y, a0[k].y, wr[k].y), d0.y, s0);
            s0 = fmaf(fmaf(ar[k].z, a0[k].z, wr[k].z), d0.z, s0);
            s0 = fmaf(fmaf(ar[k].w, a0[k].w, wr[k].w), d0.w, s0);
            s1 = fmaf(fmaf(ar[k].x, a1[k].x, wr[k].x), d1.x, s1);
            s1 = fmaf(fmaf(ar[k].y, a1[k].y, wr[k].y), d1.y, s1);
            s1 = fmaf(fmaf(ar[k].z, a1[k].z, wr[k].z), d1.z, s1);
            s1 = fmaf(fmaf(ar[k].w, a1[k].w, wr[k].w), d1.w, s1);
        }
#pragma unroll
        for (int k = 0; k < 2; ++k) {
            const float4 x0 = shX[bb * (IN / 4) + lane + 32 * k];
            const float4 x1 = shX[(bb + 1) * (IN / 4) + lane + 32 * k];
            s0 = fmaf(iw[k].x, x0.x, s0); s0 = fmaf(iw[k].y, x0.y, s0);
            s0 = fmaf(iw[k].z, x0.z, s0); s0 = fmaf(iw[k].w, x0.w, s0);
            s1 = fmaf(iw[k].x, x1.x, s1); s1 = fmaf(iw[k].y, x1.y, s1);
            s1 = fmaf(iw[k].z, x1.z, s1); s1 = fmaf(iw[k].w, x1.w, s1);
        }
#pragma unroll
        for (int off = 16; off; off >>= 1) {
            s0 += __shfl_xor_sync(0xffffffffu, s0, off);
            s1 += __shfl_xor_sync(0xffffffffu, s1, off);
        }
        if (lane == 0) {
            const float h0v = tanhf(s0 + bias);
            const float h1v = tanhf(s1 + bias);
            hactiv[(size_t)(bbase + bb)     * HS + i] = h0v;
            hactiv[(size_t)(bbase + bb + 1) * HS + i] = h1v;
            sh_hact[bb * RG + warp]       = h0v;
            sh_hact[(bb + 1) * RG + warp] = h1v;
        }
    }
    __syncthreads();

    // ---------------- da partials + counter (release) ----------------
    if (tid < SG) {
        const int b = bbase + tid;
        float sum = 0.f;
#pragma unroll
        for (int wv = 0; wv < RG; ++wv) sum += sh_wda[wv] * sh_hact[tid * RG + wv];
        atomicAdd(&g_acc_da[b], sum);
        __threadfence();
        atomicAdd(&g_cnt[b], 1u);
    }

    // ---------------- spin (acquire), then consume + self-reset ----------
    if (tid < SG) {
        const int b = bbase + tid;
        unsigned c;
        do {
            asm volatile("ld.acquire.gpu.u32 %0, [%1];" : "=r"(c) : "l"(g_cnt + b));
            if (c < NCTA_PER_SAMPLE) __nanosleep(64);
        } while (c < NCTA_PER_SAMPLE);
        sh_da[tid] = tanhf(__ldcg(&g_acc_da[b]) + h2da_b[0]);
        // self-reset: last consumer of this sample zeroes the slots
        const unsigned old = atomicAdd(&g_done[b], 1u);
        if (old == NCTA_PER_SAMPLE - 1) {
            g_acc_da[b] = 0.f;
            g_cnt[b]    = 0u;
            __threadfence();
            g_done[b]   = 0u;
        }
    }
    __syncthreads();

    // ---------------- phase 3: hebb update ----------------
#pragma unroll 2
    for (int bb = 0; bb < SG; ++bb) {
        const float coef = sh_da[bb] * sh_hact[bb * RG + warp];
        const size_t roff = ((size_t)(bbase + bb) * HS + i) * HS;
        const float4* hb = (const float4*)(hebb + roff);
        float4*       ob = (float4*)(hebb_new + roff);
#pragma unroll
        for (int k = 0; k < 4; ++k) {
            const float4 h = __ldcs(hb + lane + 32 * k);
            const float4 x = shH[bb * (HS / 4) + lane + 32 * k];
            float4 r;
            r.x = fminf(1.f, fmaxf(-1.f, fmaf(coef, x.x, h.x)));
            r.y = fminf(1.f, fmaxf(-1.f, fmaf(coef, x.y, h.y)));
            r.z = fminf(1.f, fmaxf(-1.f, fmaf(coef, x.z, h.z)));
            r.w = fminf(1.f, fmaxf(-1.f, fmaf(coef, x.w, h.w)));
            __stcs(ob + lane + 32 * k, r);
        }
    }

    // ---------------- fused heads (hactiv of this group is L2-hot) --------
    const int x = blockIdx.x;
    if (x < OUT / RG) {                         // x in [0,32): activout
        const int o = x * RG + warp;
        const float4* wrow = (const float4*)(h2o_w + (size_t)o * HS);
        float4 wv[4];
#pragma unroll
        for (int k = 0; k < 4; ++k) wv[k] = wrow[lane + 32 * k];
        const float obias = h2o_b[o];
#pragma unroll 2
        for (int bb = 0; bb < SG; ++bb) {
            const float4* ha = (const float4*)(hactiv + (size_t)(bbase + bb) * HS);
            float s = 0.f;
#pragma unroll
            for (int k = 0; k < 4; ++k) {
                const float4 h = ha[lane + 32 * k];
                s = fmaf(wv[k].x, h.x, s); s = fmaf(wv[k].y, h.y, s);
                s = fmaf(wv[k].z, h.z, s); s = fmaf(wv[k].w, h.w, s);
            }
#pragma unroll
            for (int off = 16; off; off >>= 1) s += __shfl_xor_sync(0xffffffffu, s, off);
            if (lane == 0) activout[(size_t)(bbase + bb) * OUT + o] = s + obias;
        }
    } else if (x == OUT / RG) {                 // x == 32: valueout
        const int b = bbase + warp;
        const float4* vw = (const float4*)h2v_w;
        const float4* ha = (const float4*)(hactiv + (size_t)b * HS);
        float s = 0.f;
#pragma unroll
        for (int k = 0; k < 4; ++k) {
            const float4 v = vw[lane + 32 * k];
            const float4 h = ha[lane + 32 * k];
            s = fmaf(v.x, h.x, s); s = fmaf(v.y, h.y, s);
            s = fmaf(v.z, h.z, s); s = fmaf(v.w, h.w, s);
        }
#pragma unroll
        for (int off = 16; off; off >>= 1) s += __shfl_xor_sync(0xffffffffu, s, off);
        if (lane == 0) valueout[b] = s + h2v_b[0];
    }
}

// ---------------------------------------------------------------------------
extern "C" void kernel_launch(void* const* d_in, const int* in_sizes, int n_in,
                              void* d_out, int out_size)
{
    const float* inputs = (const float*)d_in[0];
    const float* hidden = (const float*)d_in[1];
    const float* hebb   = (const float*)d_in[2];
    const float* i2h_w  = (const float*)d_in[3];
    const float* i2h_b  = (const float*)d_in[4];
    const float* w      = (const float*)d_in[5];
    const float* alpha  = (const float*)d_in[6];
    const float* h2o_w  = (const float*)d_in[7];
    const float* h2o_b  = (const float*)d_in[8];
    const float* h2v_w  = (const float*)d_in[9];
    const float* h2v_b  = (const float*)d_in[10];
    const float* h2da_w = (const float*)d_in[11];
    const float* h2da_b = (const float*)d_in[12];

    float* out      = (float*)d_out;
    float* activout = out;                                // [B, OUT]
    float* valueout = activout + (size_t)B * OUT;         // [B, 1]
    float* hactiv   = valueout + B;                       // [B, HS]
    float* hebb_new = hactiv + (size_t)B * HS;            // [B, HS, HS]

    k1_fused<<<dim3(HS / RG, B / SG), 256>>>(
        inputs, hidden, hebb, i2h_w, i2h_b, w, alpha,
        h2da_w, h2da_b, h2o_w, h2o_b, h2v_w, h2v_b,
        hactiv, hebb_new, activout, valueout);
}

// round 8
// speedup vs baseline: 2.4814x; 1.0094x over previous
#include <cuda_runtime.h>

#define B      128
#define IN     256
#define HS     512
#define OUT    256
#define RG     8      // rows per CTA (one warp per row)
#define SG     8      // samples per CTA
#define NCTA_PER_SAMPLE (HS / RG)   // 64

__device__ float        g_acc_da[B];   // zeroed at load; left zero by kernel
__device__ unsigned int g_cnt[B];
__device__ unsigned int g_done[B];

// ---------------------------------------------------------------------------
// Fused kernel, 3 CTAs/SM target:
//  w/alpha rows live in SMEM (not regs) to cut register pressure;
//  hidden comes from gmem (fully L2-resident, 256 KB);
//  phase 1 -> da partials -> spin -> phase 3 (reversed) -> fused heads.
// ---------------------------------------------------------------------------
__global__ __launch_bounds__(256, 3) void k1_fused(
    const float* __restrict__ inputs, const float* __restrict__ hidden,
    const float* __restrict__ hebb,   const float* __restrict__ i2h_w,
    const float* __restrict__ i2h_b,  const float* __restrict__ w,
    const float* __restrict__ alpha,  const float* __restrict__ h2da_w,
    const float* __restrict__ h2da_b, const float* __restrict__ h2o_w,
    const float* __restrict__ h2o_b,  const float* __restrict__ h2v_w,
    const float* __restrict__ h2v_b,  float* __restrict__ hactiv,
    float* __restrict__ hebb_new,     float* __restrict__ activout,
    float* __restrict__ valueout)
{
    const int tid   = threadIdx.x;
    const int warp  = tid >> 5;
    const int lane  = tid & 31;
    const int i     = blockIdx.x * RG + warp;
    const int bbase = blockIdx.y * SG;

    __shared__ float4 shW[RG * HS / 4];    // 16 KB: this CTA's 8 w-rows
    __shared__ float4 shA[RG * HS / 4];    // 16 KB: this CTA's 8 alpha-rows
    __shared__ float4 shX[SG * IN / 4];    //  8 KB: 8 samples' inputs
    __shared__ float  sh_hact[SG * RG];
    __shared__ float  sh_wda[RG];
    __shared__ float  sh_da[SG];

    // preload weights + inputs (w/alpha slices are L2-hot across y-CTAs)
    const float4* gw = (const float4*)(w     + (size_t)blockIdx.x * RG * HS);
    const float4* ga = (const float4*)(alpha + (size_t)blockIdx.x * RG * HS);
    for (int t = tid; t < RG * HS / 4; t += 256) { shW[t] = gw[t]; shA[t] = ga[t]; }
    const float4* gx = (const float4*)(inputs + (size_t)bbase * IN);
    for (int t = tid; t < SG * IN / 4; t += 256) shX[t] = gx[t];
    if (tid < RG) sh_wda[tid] = h2da_w[blockIdx.x * RG + tid];

    float4 iw[2];
    const float4* x4 = (const float4*)(i2h_w + (size_t)i * IN);
#pragma unroll
    for (int k = 0; k < 2; ++k) iw[k] = x4[lane + 32 * k];
    const float bias = i2h_b[i];

    __syncthreads();

    // ---------------- phase 1: hactiv ----------------
#pragma unroll
    for (int bb = 0; bb < SG; bb += 2) {
        const float4* h0 = (const float4*)(hebb + ((size_t)(bbase + bb)     * HS + i) * HS);
        const float4* h1 = (const float4*)(hebb + ((size_t)(bbase + bb + 1) * HS + i) * HS);
        const float4* q0 = (const float4*)(hidden + (size_t)(bbase + bb)     * HS);
        const float4* q1 = (const float4*)(hidden + (size_t)(bbase + bb + 1) * HS);

        float4 a0[4], a1[4];
#pragma unroll
        for (int k = 0; k < 4; ++k) { a0[k] = h0[lane + 32 * k]; a1[k] = h1[lane + 32 * k]; }

        float s0 = 0.f, s1 = 0.f;
#pragma unroll
        for (int k = 0; k < 4; ++k) {
            const float4 wv = shW[warp * (HS / 4) + lane + 32 * k];
            const float4 av = shA[warp * (HS / 4) + lane + 32 * k];
            const float4 d0 = __ldg(q0 + lane + 32 * k);
            const float4 d1 = __ldg(q1 + lane + 32 * k);
            s0 = fmaf(fmaf(av.x, a0[k].x, wv.x), d0.x, s0);
            s0 = fmaf(fmaf(av.y, a0[k].y, wv.y), d0.y, s0);
            s0 = fmaf(fmaf(av.z, a0[k].z, wv.z), d0.z, s0);
            s0 = fmaf(fmaf(av.w, a0[k].w, wv.w), d0.w, s0);
            s1 = fmaf(fmaf(av.x, a1[k].x, wv.x), d1.x, s1);
            s1 = fmaf(fmaf(av.y, a1[k].y, wv.y), d1.y, s1);
            s1 = fmaf(fmaf(av.z, a1[k].z, wv.z), d1.z, s1);
            s1 = fmaf(fmaf(av.w, a1[k].w, wv.w), d1.w, s1);
        }
#pragma unroll
        for (int k = 0; k < 2; ++k) {
            const float4 x0 = shX[bb * (IN / 4) + lane + 32 * k];
            const float4 x1 = shX[(bb + 1) * (IN / 4) + lane + 32 * k];
            s0 = fmaf(iw[k].x, x0.x, s0); s0 = fmaf(iw[k].y, x0.y, s0);
            s0 = fmaf(iw[k].z, x0.z, s0); s0 = fmaf(iw[k].w, x0.w, s0);
            s1 = fmaf(iw[k].x, x1.x, s1); s1 = fmaf(iw[k].y, x1.y, s1);
            s1 = fmaf(iw[k].z, x1.z, s1); s1 = fmaf(iw[k].w, x1.w, s1);
        }
#pragma unroll
        for (int off = 16; off; off >>= 1) {
            s0 += __shfl_xor_sync(0xffffffffu, s0, off);
            s1 += __shfl_xor_sync(0xffffffffu, s1, off);
        }
        if (lane == 0) {
            const float h0v = tanhf(s0 + bias);
            const float h1v = tanhf(s1 + bias);
            hactiv[(size_t)(bbase + bb)     * HS + i] = h0v;
            hactiv[(size_t)(bbase + bb + 1) * HS + i] = h1v;
            sh_hact[bb * RG + warp]       = h0v;
            sh_hact[(bb + 1) * RG + warp] = h1v;
        }
    }
    __syncthreads();

    // ---------------- da partials + counter (release) ----------------
    if (tid < SG) {
        const int b = bbase + tid;
        float sum = 0.f;
#pragma unroll
        for (int wv = 0; wv < RG; ++wv) sum += sh_wda[wv] * sh_hact[tid * RG + wv];
        atomicAdd(&g_acc_da[b], sum);
        __threadfence();
        atomicAdd(&g_cnt[b], 1u);
    }

    // ---------------- spin (acquire), consume, self-reset ----------------
    if (tid < SG) {
        const int b = bbase + tid;
        unsigned c;
        do {
            asm volatile("ld.acquire.gpu.u32 %0, [%1];" : "=r"(c) : "l"(g_cnt + b));
            if (c < NCTA_PER_SAMPLE) __nanosleep(64);
        } while (c < NCTA_PER_SAMPLE);
        sh_da[tid] = tanhf(__ldcg(&g_acc_da[b]) + h2da_b[0]);
        const unsigned old = atomicAdd(&g_done[b], 1u);
        if (old == NCTA_PER_SAMPLE - 1) {
            g_acc_da[b] = 0.f;
            g_cnt[b]    = 0u;
            __threadfence();
            g_done[b]   = 0u;
        }
    }
    __syncthreads();

    // ---------------- phase 3: hebb update (reversed for locality) --------
#pragma unroll 2
    for (int bb = SG - 1; bb >= 0; --bb) {
        const float coef = sh_da[bb] * sh_hact[bb * RG + warp];
        const size_t roff = ((size_t)(bbase + bb) * HS + i) * HS;
        const float4* hb = (const float4*)(hebb + roff);
        float4*       ob = (float4*)(hebb_new + roff);
        const float4* q  = (const float4*)(hidden + (size_t)(bbase + bb) * HS);
#pragma unroll
        for (int k = 0; k < 4; ++k) {
            const float4 h = __ldcs(hb + lane + 32 * k);
            const float4 x = __ldg(q + lane + 32 * k);
            float4 r;
            r.x = fminf(1.f, fmaxf(-1.f, fmaf(coef, x.x, h.x)));
            r.y = fminf(1.f, fmaxf(-1.f, fmaf(coef, x.y, h.y)));
            r.z = fminf(1.f, fmaxf(-1.f, fmaf(coef, x.z, h.z)));
            r.w = fminf(1.f, fmaxf(-1.f, fmaf(coef, x.w, h.w)));
            __stcs(ob + lane + 32 * k, r);
        }
    }

    // ---------------- fused heads (hactiv is L2-hot) ----------------------
    const int x = blockIdx.x;
    if (x < OUT / RG) {                         // x in [0,32): activout
        const int o = x * RG + warp;
        const float4* wrow = (const float4*)(h2o_w + (size_t)o * HS);
        float4 wv[4];
#pragma unroll
        for (int k = 0; k < 4; ++k) wv[k] = wrow[lane + 32 * k];
        const float obias = h2o_b[o];
#pragma unroll 2
        for (int bb = 0; bb < SG; ++bb) {
            const float4* ha = (const float4*)(hactiv + (size_t)(bbase + bb) * HS);
            float s = 0.f;
#pragma unroll
            for (int k = 0; k < 4; ++k) {
                const float4 h = ha[lane + 32 * k];
                s = fmaf(wv[k].x, h.x, s); s = fmaf(wv[k].y, h.y, s);
                s = fmaf(wv[k].z, h.z, s); s = fmaf(wv[k].w, h.w, s);
            }
#pragma unroll
            for (int off = 16; off; off >>= 1) s += __shfl_xor_sync(0xffffffffu, s, off);
            if (lane == 0) activout[(size_t)(bbase + bb) * OUT + o] = s + obias;
        }
    } else if (x == OUT / RG) {                 // x == 32: valueout
        const int b = bbase + warp;
        const float4* vw = (const float4*)h2v_w;
        const float4* ha = (const float4*)(hactiv + (size_t)b * HS);
        float s = 0.f;
#pragma unroll
        for (int k = 0; k < 4; ++k) {
            const float4 v = vw[lane + 32 * k];
            const float4 h = ha[lane + 32 * k];
            s = fmaf(v.x, h.x, s); s = fmaf(v.y, h.y, s);
            s = fmaf(v.z, h.z, s); s = fmaf(v.w, h.w, s);
        }
#pragma unroll
        for (int off = 16; off; off >>= 1) s += __shfl_xor_sync(0xffffffffu, s, off);
        if (lane == 0) valueout[b] = s + h2v_b[0];
    }
}

// ---------------------------------------------------------------------------
extern "C" void kernel_launch(void* const* d_in, const int* in_sizes, int n_in,
                              void* d_out, int out_size)
{
    const float* inputs = (const float*)d_in[0];
    const float* hidden = (const float*)d_in[1];
    const float* hebb   = (const float*)d_in[2];
    const float* i2h_w  = (const float*)d_in[3];
    const float* i2h_b  = (const float*)d_in[4];
    const float* w      = (const float*)d_in[5];
    const float* alpha  = (const float*)d_in[6];
    const float* h2o_w  = (const float*)d_in[7];
    const float* h2o_b  = (const float*)d_in[8];
    const float* h2v_w  = (const float*)d_in[9];
    const float* h2v_b  = (const float*)d_in[10];
    const float* h2da_w = (const float*)d_in[11];
    const float* h2da_b = (const float*)d_in[12];

    float* out      = (float*)d_out;
    float* activout = out;                                // [B, OUT]
    float* valueout = activout + (size_t)B * OUT;         // [B, 1]
    float* hactiv   = valueout + B;                       // [B, HS]
    float* hebb_new = hactiv + (size_t)B * HS;            // [B, HS, HS]

    k1_fused<<<dim3(HS / RG, B / SG), 256>>>(
        inputs, hidden, hebb, i2h_w, i2h_b, w, alpha,
        h2da_w, h2da_b, h2o_w, h2o_b, h2v_w, h2v_b,
        hactiv, hebb_new, activout, valueout);
}